// round 5
// baseline (speedup 1.0000x reference)
#include <cuda_runtime.h>

// Replicates XLA:CPU (aarch64) math lowering bit-for-bit:
//  - cephes/Eigen exp & log (llvm_ir_runtime), FMA in Horner (NEON pmadd),
//    separate mul/sub elsewhere
//  - XLA log1p: u=1+x; u==1 ? x : log(u)*(x/(u-1))
//  - XLA fast tanh rational (clamp +-7.90531110763549805)
//  - logistic expander: 1/(1+exp(-x))
//  - NO FMA contraction in HLO-level arithmetic (explicit __fmul_rn/__fadd_rn)

#define FULLMASK 0xFFFFFFFFu
#define NWARPS 8
#define KMIX 10
#define HW 1024
#define LOG127_5 4.8481163645984802f

__device__ __forceinline__ float xla_exp(float x) {
    x = fminf(fmaxf(x, -88.3762626647949f), 88.3762626647950f);
    float fx = floorf(__fmaf_rn(x, 1.44269504088896341f, 0.5f));
    float r = __fsub_rn(x, __fmul_rn(fx, 0.693359375f));
    r = __fsub_rn(r, __fmul_rn(fx, -2.12194440e-4f));
    float z = __fmul_rn(r, r);
    float y = 1.9875691500E-4f;
    y = __fmaf_rn(y, r, 1.3981999507E-3f);
    y = __fmaf_rn(y, r, 8.3334519073E-3f);
    y = __fmaf_rn(y, r, 4.1665795894E-2f);
    y = __fmaf_rn(y, r, 1.6666665459E-1f);
    y = __fmaf_rn(y, r, 5.0000001201E-1f);
    y = __fmaf_rn(y, z, r);
    y = __fadd_rn(y, 1.0f);
    int n = (int)fx;                       // fx in [-127, 127]
    float p2n = __int_as_float((n + 127) << 23);   // n=-127 -> 0.0 (flush)
    return __fmul_rn(y, p2n);
}

__device__ __forceinline__ float xla_log(float x) {
    // assumes x > 0, normal (all call sites have x >= ~1e-12)
    int bits = __float_as_int(x);
    float e = (float)((bits >> 23) - 126);
    float m = __int_as_float((bits & 0x007fffff) | 0x3f000000);  // [0.5, 1)
    if (m < 0.707106781186547524f) {
        e = __fsub_rn(e, 1.0f);
        m = __fadd_rn(__fsub_rn(m, 1.0f), m);   // (m-1)+m
    } else {
        m = __fsub_rn(m, 1.0f);
    }
    float z = __fmul_rn(m, m);
    float y = 7.0376836292E-2f;
    y = __fmaf_rn(y, m, -1.1514610310E-1f);
    y = __fmaf_rn(y, m, 1.1676998740E-1f);
    y = __fmaf_rn(y, m, -1.2420140846E-1f);
    y = __fmaf_rn(y, m, 1.4249322787E-1f);
    y = __fmaf_rn(y, m, -1.6668057665E-1f);
    y = __fmaf_rn(y, m, 2.0000714765E-1f);
    y = __fmaf_rn(y, m, -2.4999993993E-1f);
    y = __fmaf_rn(y, m, 3.3333331174E-1f);
    y = __fmul_rn(y, m);
    y = __fmul_rn(y, z);
    y = __fadd_rn(y, __fmul_rn(e, -2.12194440e-4f));
    y = __fsub_rn(y, __fmul_rn(z, 0.5f));
    float res = __fadd_rn(m, y);
    res = __fadd_rn(res, __fmul_rn(e, 0.693359375f));
    return res;
}

__device__ __forceinline__ float xla_log1p(float x) {
    float u = __fadd_rn(x, 1.0f);
    float w = __fmul_rn(xla_log(u), __fdiv_rn(x, __fsub_rn(u, 1.0f)));
    return (u == 1.0f) ? x : w;
}

// XLA fast tanh rational (MulAdd -> FMA), clamp +-7.90531110763549805
__device__ __forceinline__ float xla_tanh(float x) {
    float xc = fminf(fmaxf(x, -7.90531110763549805f), 7.90531110763549805f);
    float x2 = __fmul_rn(xc, xc);
    float p = -2.76076847742355e-16f;
    p = __fmaf_rn(p, x2, 2.00018790482477e-13f);
    p = __fmaf_rn(p, x2, -8.60467152213735e-11f);
    p = __fmaf_rn(p, x2, 5.12229709037114e-08f);
    p = __fmaf_rn(p, x2, 1.48572235717979e-05f);
    p = __fmaf_rn(p, x2, 6.37261928875436e-04f);
    p = __fmaf_rn(p, x2, 4.89352455891786e-03f);
    float num = __fmul_rn(xc, p);
    float q = 1.19825839466702e-06f;
    q = __fmaf_rn(q, x2, 1.18534705686654e-04f);
    q = __fmaf_rn(q, x2, 2.26843463243900e-03f);
    q = __fmaf_rn(q, x2, 4.89352518554385e-03f);
    float r = __fdiv_rn(num, q);
    return (fabsf(x) < 0.0004f) ? x : r;
}

// logistic expander: 1 / (1 + exp(-x))
__device__ __forceinline__ float xla_sigmoid(float x) {
    return __fdiv_rn(1.0f, __fadd_rn(1.0f, xla_exp(-x)));
}

// softplus = logaddexp(x,0) = max(x,0) + log1p(exp(-|x|))
__device__ __forceinline__ float xla_softplus(float x) {
    return __fadd_rn(fmaxf(x, 0.0f), xla_log1p(xla_exp(-fabsf(x))));
}

__device__ __forceinline__ float bin_logprob(int t, float m, float iv, float s) {
    if (t == 0) {
        float n0 = __fmul_rn(__fsub_rn(-0.9921875f, m), iv);   // colors[1]
        return __fsub_rn(n0, xla_softplus(n0));
    }
    if (t == 255) {
        float n = __fmul_rn(__fsub_rn(0.9921875f, m), iv);     // colors[255]
        return -xla_softplus(n);
    }
    float clo = __fadd_rn(__fmul_rn((float)t, 0.0078125f), -1.0f);       // exact
    float chi = __fadd_rn(__fmul_rn((float)(t + 1), 0.0078125f), -1.0f); // exact
    float shi = xla_sigmoid(__fmul_rn(__fsub_rn(chi, m), iv));
    float slo = xla_sigmoid(__fmul_rn(__fsub_rn(clo, m), iv));
    float pdf = __fsub_rn(shi, slo);
    if (pdf > 1e-5f) {
        return xla_log(fmaxf(pdf, 1e-12f));
    }
    float midc = __fadd_rn(__fmul_rn((float)(2 * t + 1), 0.00390625f), -1.0f); // exact
    float mid = __fmul_rn(__fsub_rn(midc, m), iv);
    float mlp = __fsub_rn(__fsub_rn(mid, s), __fmul_rn(2.0f, xla_softplus(mid)));
    return __fsub_rn(mlp, LOG127_5);
}

__global__ __launch_bounds__(32 * NWARPS)
void mixlogistic_decode_kernel(const float* __restrict__ x,
                               const float* __restrict__ l,
                               const int* __restrict__ epsp,
                               float* __restrict__ out,
                               int npix)
{
    __shared__ float sLOG[NWARPS][KMIX];
    __shared__ float sLPI[NWARPS][KMIX];
    __shared__ float sM  [NWARPS][3][KMIX];
    __shared__ float sS  [NWARPS][3][KMIX];
    __shared__ float sINV[NWARPS][3][KMIX];
    __shared__ float sCF [NWARPS][3][KMIX];
    __shared__ float sRED[NWARPS][2];

    const int warp = threadIdx.x >> 5;
    const int lane = threadIdx.x & 31;
    const int P = blockIdx.x * NWARPS + warp;
    if (P >= npix) return;

    const int b  = P >> 10;
    const int hw = P & (HW - 1);

    for (int c = lane; c < 100; c += 32) {
        float v = l[(size_t)(b * 100 + c) * HW + hw];
        if (c < KMIX) {
            sLOG[warp][c] = v;
        } else {
            int cc  = (c - KMIX) / 30;
            int rem = (c - KMIX) % 30;
            int grp = rem / KMIX;
            int k   = rem % KMIX;
            if (grp == 0) {
                sM[warp][cc][k] = v;
            } else if (grp == 1) {
                float s = fmaxf(v, -7.0f);
                sS[warp][cc][k]   = s;
                sINV[warp][cc][k] = xla_exp(-s);
            } else {
                sCF[warp][cc][k] = xla_tanh(v);
            }
        }
    }
    __syncwarp();
    if (lane == 0) {
        float mx = sLOG[warp][0];
        #pragma unroll
        for (int k = 1; k < KMIX; k++) mx = fmaxf(mx, sLOG[warp][k]);
        float sum = 0.0f;
        #pragma unroll
        for (int k = 0; k < KMIX; k++)
            sum = __fadd_rn(sum, xla_exp(__fsub_rn(sLOG[warp][k], mx)));
        sRED[warp][0] = mx;
        sRED[warp][1] = xla_log(sum);
    }
    __syncwarp();
    if (lane < KMIX) {
        sLPI[warp][lane] = __fsub_rn(__fsub_rn(sLOG[warp][lane], sRED[warp][0]),
                                     sRED[warp][1]);
    }
    __syncwarp();

    const int eps = epsp[0];
    float xr = 0.0f, xg = 0.0f;

    #pragma unroll
    for (int c = 0; c < 3; c++) {
        float xorig = x[(size_t)(b * 3 + c) * HW + hw];
        int r  = (int)(__fadd_rn(__fmul_rn(xorig, 127.5f), 127.5f)); // no FMA + trunc
        int lb = max(r - eps, 0);
        int ub = min(r + eps, 255);

        int t0 = lb + lane;
        int t1 = t0 + 32;
        bool v0 = (t0 <= ub);
        bool v1 = (t1 <= ub);

        float lp0[KMIX], lp1[KMIX];

        #pragma unroll
        for (int k = 0; k < KMIX; k++) {
            float m = sM[warp][c][k];
            if (c == 1) {
                m = __fadd_rn(m, __fmul_rn(sCF[warp][0][k], xr));
            } else if (c == 2) {
                m = __fadd_rn(m, __fmul_rn(sCF[warp][1][k], xr));
                m = __fadd_rn(m, __fmul_rn(sCF[warp][2][k], xg));
            }
            float iv  = sINV[warp][c][k];
            float s   = sS[warp][c][k];
            float lpi = sLPI[warp][k];
            if (v0) lp0[k] = __fadd_rn(bin_logprob(t0, m, iv, s), lpi);
            if (v1) lp1[k] = __fadd_rn(bin_logprob(t1, m, iv, s), lpi);
        }

        float bv = -INFINITY;
        int   bt = 0x7FFFFFFF;
        if (v0) {
            float amax = lp0[0];
            #pragma unroll
            for (int k = 1; k < KMIX; k++) amax = fmaxf(amax, lp0[k]);
            float sum = 0.0f;
            #pragma unroll
            for (int k = 0; k < KMIX; k++)
                sum = __fadd_rn(sum, xla_exp(__fsub_rn(lp0[k], amax)));
            bv = __fadd_rn(xla_log(sum), amax);
            bt = t0;
        }
        if (v1) {
            float amax = lp1[0];
            #pragma unroll
            for (int k = 1; k < KMIX; k++) amax = fmaxf(amax, lp1[k]);
            float sum = 0.0f;
            #pragma unroll
            for (int k = 0; k < KMIX; k++)
                sum = __fadd_rn(sum, xla_exp(__fsub_rn(lp1[k], amax)));
            float val = __fadd_rn(xla_log(sum), amax);
            if (val > bv) { bv = val; bt = t1; }
        }

        #pragma unroll
        for (int off = 16; off; off >>= 1) {
            float ov = __shfl_down_sync(FULLMASK, bv, off);
            int   ot = __shfl_down_sync(FULLMASK, bt, off);
            if (ov > bv || (ov == bv && ot < bt)) { bv = ov; bt = ot; }
        }
        bt = __shfl_sync(FULLMASK, bt, 0);

        float outv = __fdiv_rn(__fsub_rn((float)bt, 127.5f), 127.5f);
        if (c == 0) xr = outv;
        else if (c == 1) xg = outv;

        if (lane == 0) {
            out[(size_t)(b * 3 + c) * HW + hw] = outv;
        }
    }
}

extern "C" void kernel_launch(void* const* d_in, const int* in_sizes, int n_in,
                              void* d_out, int out_size)
{
    const float* x   = (const float*)d_in[0];
    const float* l   = (const float*)d_in[1];
    const int*   eps = (const int*)d_in[2];
    float* out = (float*)d_out;

    int npix = in_sizes[0] / 3;
    int blocks = (npix + NWARPS - 1) / NWARPS;
    mixlogistic_decode_kernel<<<blocks, 32 * NWARPS>>>(x, l, eps, out, npix);
}

// round 6
// speedup vs baseline: 1.5997x; 1.5997x over previous
#include <cuda_runtime.h>

// Math replicates XLA:CPU cephes/Eigen lowering bit-for-bit (validated R5).
// DO NOT alter any arithmetic in xla_* or bin_logprob — correctness depends on
// bitwise match (argmax ties are decided at ULP level).

#define FULLMASK 0xFFFFFFFFu
#define NWARPS 8
#define KMIX 10
#define HW 1024
#define LOG127_5 4.8481163645984802f

__device__ __forceinline__ float xla_exp(float x) {
    x = fminf(fmaxf(x, -88.3762626647949f), 88.3762626647950f);
    float fx = floorf(__fmaf_rn(x, 1.44269504088896341f, 0.5f));
    float r = __fsub_rn(x, __fmul_rn(fx, 0.693359375f));
    r = __fsub_rn(r, __fmul_rn(fx, -2.12194440e-4f));
    float z = __fmul_rn(r, r);
    float y = 1.9875691500E-4f;
    y = __fmaf_rn(y, r, 1.3981999507E-3f);
    y = __fmaf_rn(y, r, 8.3334519073E-3f);
    y = __fmaf_rn(y, r, 4.1665795894E-2f);
    y = __fmaf_rn(y, r, 1.6666665459E-1f);
    y = __fmaf_rn(y, r, 5.0000001201E-1f);
    y = __fmaf_rn(y, z, r);
    y = __fadd_rn(y, 1.0f);
    int n = (int)fx;
    float p2n = __int_as_float((n + 127) << 23);
    return __fmul_rn(y, p2n);
}

__device__ __forceinline__ float xla_log(float x) {
    int bits = __float_as_int(x);
    float e = (float)((bits >> 23) - 126);
    float m = __int_as_float((bits & 0x007fffff) | 0x3f000000);
    if (m < 0.707106781186547524f) {
        e = __fsub_rn(e, 1.0f);
        m = __fadd_rn(__fsub_rn(m, 1.0f), m);
    } else {
        m = __fsub_rn(m, 1.0f);
    }
    float z = __fmul_rn(m, m);
    float y = 7.0376836292E-2f;
    y = __fmaf_rn(y, m, -1.1514610310E-1f);
    y = __fmaf_rn(y, m, 1.1676998740E-1f);
    y = __fmaf_rn(y, m, -1.2420140846E-1f);
    y = __fmaf_rn(y, m, 1.4249322787E-1f);
    y = __fmaf_rn(y, m, -1.6668057665E-1f);
    y = __fmaf_rn(y, m, 2.0000714765E-1f);
    y = __fmaf_rn(y, m, -2.4999993993E-1f);
    y = __fmaf_rn(y, m, 3.3333331174E-1f);
    y = __fmul_rn(y, m);
    y = __fmul_rn(y, z);
    y = __fadd_rn(y, __fmul_rn(e, -2.12194440e-4f));
    y = __fsub_rn(y, __fmul_rn(z, 0.5f));
    float res = __fadd_rn(m, y);
    res = __fadd_rn(res, __fmul_rn(e, 0.693359375f));
    return res;
}

__device__ __forceinline__ float xla_log1p(float x) {
    float u = __fadd_rn(x, 1.0f);
    float w = __fmul_rn(xla_log(u), __fdiv_rn(x, __fsub_rn(u, 1.0f)));
    return (u == 1.0f) ? x : w;
}

__device__ __forceinline__ float xla_tanh(float x) {
    float xc = fminf(fmaxf(x, -7.90531110763549805f), 7.90531110763549805f);
    float x2 = __fmul_rn(xc, xc);
    float p = -2.76076847742355e-16f;
    p = __fmaf_rn(p, x2, 2.00018790482477e-13f);
    p = __fmaf_rn(p, x2, -8.60467152213735e-11f);
    p = __fmaf_rn(p, x2, 5.12229709037114e-08f);
    p = __fmaf_rn(p, x2, 1.48572235717979e-05f);
    p = __fmaf_rn(p, x2, 6.37261928875436e-04f);
    p = __fmaf_rn(p, x2, 4.89352455891786e-03f);
    float num = __fmul_rn(xc, p);
    float q = 1.19825839466702e-06f;
    q = __fmaf_rn(q, x2, 1.18534705686654e-04f);
    q = __fmaf_rn(q, x2, 2.26843463243900e-03f);
    q = __fmaf_rn(q, x2, 4.89352518554385e-03f);
    float r = __fdiv_rn(num, q);
    return (fabsf(x) < 0.0004f) ? x : r;
}

__device__ __forceinline__ float xla_sigmoid(float x) {
    return __fdiv_rn(1.0f, __fadd_rn(1.0f, xla_exp(-x)));
}

__device__ __forceinline__ float xla_softplus(float x) {
    return __fadd_rn(fmaxf(x, 0.0f), xla_log1p(xla_exp(-fabsf(x))));
}

__device__ __forceinline__ float bin_logprob(int t, float m, float iv, float s) {
    if (t == 0) {
        float n0 = __fmul_rn(__fsub_rn(-0.9921875f, m), iv);
        return __fsub_rn(n0, xla_softplus(n0));
    }
    if (t == 255) {
        float n = __fmul_rn(__fsub_rn(0.9921875f, m), iv);
        return -xla_softplus(n);
    }
    float clo = __fadd_rn(__fmul_rn((float)t, 0.0078125f), -1.0f);
    float chi = __fadd_rn(__fmul_rn((float)(t + 1), 0.0078125f), -1.0f);
    float shi = xla_sigmoid(__fmul_rn(__fsub_rn(chi, m), iv));
    float slo = xla_sigmoid(__fmul_rn(__fsub_rn(clo, m), iv));
    float pdf = __fsub_rn(shi, slo);
    if (pdf > 1e-5f) {
        return xla_log(fmaxf(pdf, 1e-12f));
    }
    float midc = __fadd_rn(__fmul_rn((float)(2 * t + 1), 0.00390625f), -1.0f);
    float mid = __fmul_rn(__fsub_rn(midc, m), iv);
    float mlp = __fsub_rn(__fsub_rn(mid, s), __fmul_rn(2.0f, xla_softplus(mid)));
    return __fsub_rn(mlp, LOG127_5);
}

__global__ __launch_bounds__(32 * NWARPS)
void mixlogistic_decode_kernel(const float* __restrict__ x,
                               const float* __restrict__ l,
                               const int* __restrict__ epsp,
                               float* __restrict__ out,
                               int npix)
{
    __shared__ float sLOG[NWARPS][KMIX];
    __shared__ float sLPI[NWARPS][KMIX];
    __shared__ float sM  [NWARPS][3][KMIX];
    __shared__ float sS  [NWARPS][3][KMIX];
    __shared__ float sINV[NWARPS][3][KMIX];
    __shared__ float sCF [NWARPS][3][KMIX];
    __shared__ float sRED[NWARPS][2];

    const int warp = threadIdx.x >> 5;
    const int lane = threadIdx.x & 31;
    const int P = blockIdx.x * NWARPS + warp;
    if (P >= npix) return;

    const int b  = P >> 10;
    const int hw = P & (HW - 1);

    for (int c = lane; c < 100; c += 32) {
        float v = l[(size_t)(b * 100 + c) * HW + hw];
        if (c < KMIX) {
            sLOG[warp][c] = v;
        } else {
            int cc  = (c - KMIX) / 30;
            int rem = (c - KMIX) % 30;
            int grp = rem / KMIX;
            int k   = rem % KMIX;
            if (grp == 0) {
                sM[warp][cc][k] = v;
            } else if (grp == 1) {
                float s = fmaxf(v, -7.0f);
                sS[warp][cc][k]   = s;
                sINV[warp][cc][k] = xla_exp(-s);
            } else {
                sCF[warp][cc][k] = xla_tanh(v);
            }
        }
    }
    __syncwarp();
    if (lane == 0) {
        float mx = sLOG[warp][0];
        #pragma unroll
        for (int k = 1; k < KMIX; k++) mx = fmaxf(mx, sLOG[warp][k]);
        float sum = 0.0f;
        #pragma unroll
        for (int k = 0; k < KMIX; k++)
            sum = __fadd_rn(sum, xla_exp(__fsub_rn(sLOG[warp][k], mx)));
        sRED[warp][0] = mx;
        sRED[warp][1] = xla_log(sum);
    }
    __syncwarp();
    if (lane < KMIX) {
        sLPI[warp][lane] = __fsub_rn(__fsub_rn(sLOG[warp][lane], sRED[warp][0]),
                                     sRED[warp][1]);
    }
    __syncwarp();

    const int eps = epsp[0];
    float xr = 0.0f, xg = 0.0f;

    #pragma unroll
    for (int c = 0; c < 3; c++) {
        float xorig = x[(size_t)(b * 3 + c) * HW + hw];
        int r  = (int)(__fadd_rn(__fmul_rn(xorig, 127.5f), 127.5f));
        int lb = max(r - eps, 0);
        int ub = min(r + eps, 255);

        const int t0 = lb + lane;
        const bool v0 = (t0 <= ub);

        // ---- main 32 bins: one bin per lane ----
        float lp0[KMIX];
        #pragma unroll
        for (int k = 0; k < KMIX; k++) {
            float m = sM[warp][c][k];
            if (c == 1) {
                m = __fadd_rn(m, __fmul_rn(sCF[warp][0][k], xr));
            } else if (c == 2) {
                m = __fadd_rn(m, __fmul_rn(sCF[warp][1][k], xr));
                m = __fadd_rn(m, __fmul_rn(sCF[warp][2][k], xg));
            }
            if (v0) {
                lp0[k] = __fadd_rn(bin_logprob(t0, m, sINV[warp][c][k], sS[warp][c][k]),
                                   sLPI[warp][k]);
            }
        }

        float bv = -INFINITY;
        int   bt = 0x7FFFFFFF;
        if (v0) {
            float amax = lp0[0];
            #pragma unroll
            for (int k = 1; k < KMIX; k++) amax = fmaxf(amax, lp0[k]);
            float sum = 0.0f;
            #pragma unroll
            for (int k = 0; k < KMIX; k++)
                sum = __fadd_rn(sum, xla_exp(__fsub_rn(lp0[k], amax)));
            bv = __fadd_rn(xla_log(sum), amax);
            bt = t0;
        }

        // warp argmax (first-index tie semantics)
        #pragma unroll
        for (int off = 16; off; off >>= 1) {
            float ov = __shfl_down_sync(FULLMASK, bv, off);
            int   ot = __shfl_down_sync(FULLMASK, bt, off);
            if (ov > bv || (ov == bv && ot < bt)) { bv = ov; bt = ot; }
        }
        bv = __shfl_sync(FULLMASK, bv, 0);
        bt = __shfl_sync(FULLMASK, bt, 0);

        // ---- 33rd bin (t = lb+32), computed cooperatively: lane k handles
        // mixture component k. Bitwise-equivalent: max is exact (order-free),
        // the exp-sum is folded sequentially in ascending k like XLA reduce. ----
        const int te = lb + 32;
        if (te <= ub) {                       // warp-uniform condition
            float lpe = -INFINITY;
            if (lane < KMIX) {
                int k = lane;
                float m = sM[warp][c][k];
                if (c == 1) {
                    m = __fadd_rn(m, __fmul_rn(sCF[warp][0][k], xr));
                } else if (c == 2) {
                    m = __fadd_rn(m, __fmul_rn(sCF[warp][1][k], xr));
                    m = __fadd_rn(m, __fmul_rn(sCF[warp][2][k], xg));
                }
                lpe = __fadd_rn(bin_logprob(te, m, sINV[warp][c][k], sS[warp][c][k]),
                                sLPI[warp][k]);
            }
            // exact max over lanes 0..9 (others hold -INF)
            float amax = lpe;
            #pragma unroll
            for (int off = 16; off; off >>= 1)
                amax = fmaxf(amax, __shfl_xor_sync(FULLMASK, amax, off));
            float e = xla_exp(__fsub_rn(lpe, amax));   // clamped; -inf lanes harmless
            // sequential ascending-k fold, identical rounding to reference
            float sum = 0.0f;
            #pragma unroll
            for (int k = 0; k < KMIX; k++)
                sum = __fadd_rn(sum, __shfl_sync(FULLMASK, e, k));
            float val = __fadd_rn(xla_log(sum), amax);
            if (val > bv) { bv = val; bt = te; }   // te is largest index: strict >
        }

        float outv = __fdiv_rn(__fsub_rn((float)bt, 127.5f), 127.5f);
        if (c == 0) xr = outv;
        else if (c == 1) xg = outv;

        if (lane == 0) {
            out[(size_t)(b * 3 + c) * HW + hw] = outv;
        }
    }
}

extern "C" void kernel_launch(void* const* d_in, const int* in_sizes, int n_in,
                              void* d_out, int out_size)
{
    const float* x   = (const float*)d_in[0];
    const float* l   = (const float*)d_in[1];
    const int*   eps = (const int*)d_in[2];
    float* out = (float*)d_out;

    int npix = in_sizes[0] / 3;
    int blocks = (npix + NWARPS - 1) / NWARPS;
    mixlogistic_decode_kernel<<<blocks, 32 * NWARPS>>>(x, l, eps, out, npix);
}

// round 7
// speedup vs baseline: 1.9023x; 1.1892x over previous
#include <cuda_runtime.h>

// Math replicates XLA:CPU cephes/Eigen lowering bit-for-bit (validated R5/R6).
// DO NOT alter any arithmetic in xla_* — argmax ties are decided at ULP level.

#define FULLMASK 0xFFFFFFFFu
#define NWARPS 8
#define KMIX 10
#define HW 1024
#define LOG127_5 4.8481163645984802f

__device__ __forceinline__ float xla_exp(float x) {
    x = fminf(fmaxf(x, -88.3762626647949f), 88.3762626647950f);
    float fx = floorf(__fmaf_rn(x, 1.44269504088896341f, 0.5f));
    float r = __fsub_rn(x, __fmul_rn(fx, 0.693359375f));
    r = __fsub_rn(r, __fmul_rn(fx, -2.12194440e-4f));
    float z = __fmul_rn(r, r);
    float y = 1.9875691500E-4f;
    y = __fmaf_rn(y, r, 1.3981999507E-3f);
    y = __fmaf_rn(y, r, 8.3334519073E-3f);
    y = __fmaf_rn(y, r, 4.1665795894E-2f);
    y = __fmaf_rn(y, r, 1.6666665459E-1f);
    y = __fmaf_rn(y, r, 5.0000001201E-1f);
    y = __fmaf_rn(y, z, r);
    y = __fadd_rn(y, 1.0f);
    int n = (int)fx;
    float p2n = __int_as_float((n + 127) << 23);
    return __fmul_rn(y, p2n);
}

__device__ __forceinline__ float xla_log(float x) {
    int bits = __float_as_int(x);
    float e = (float)((bits >> 23) - 126);
    float m = __int_as_float((bits & 0x007fffff) | 0x3f000000);
    if (m < 0.707106781186547524f) {
        e = __fsub_rn(e, 1.0f);
        m = __fadd_rn(__fsub_rn(m, 1.0f), m);
    } else {
        m = __fsub_rn(m, 1.0f);
    }
    float z = __fmul_rn(m, m);
    float y = 7.0376836292E-2f;
    y = __fmaf_rn(y, m, -1.1514610310E-1f);
    y = __fmaf_rn(y, m, 1.1676998740E-1f);
    y = __fmaf_rn(y, m, -1.2420140846E-1f);
    y = __fmaf_rn(y, m, 1.4249322787E-1f);
    y = __fmaf_rn(y, m, -1.6668057665E-1f);
    y = __fmaf_rn(y, m, 2.0000714765E-1f);
    y = __fmaf_rn(y, m, -2.4999993993E-1f);
    y = __fmaf_rn(y, m, 3.3333331174E-1f);
    y = __fmul_rn(y, m);
    y = __fmul_rn(y, z);
    y = __fadd_rn(y, __fmul_rn(e, -2.12194440e-4f));
    y = __fsub_rn(y, __fmul_rn(z, 0.5f));
    float res = __fadd_rn(m, y);
    res = __fadd_rn(res, __fmul_rn(e, 0.693359375f));
    return res;
}

__device__ __forceinline__ float xla_log1p(float x) {
    float u = __fadd_rn(x, 1.0f);
    float w = __fmul_rn(xla_log(u), __fdiv_rn(x, __fsub_rn(u, 1.0f)));
    return (u == 1.0f) ? x : w;
}

__device__ __forceinline__ float xla_tanh(float x) {
    float xc = fminf(fmaxf(x, -7.90531110763549805f), 7.90531110763549805f);
    float x2 = __fmul_rn(xc, xc);
    float p = -2.76076847742355e-16f;
    p = __fmaf_rn(p, x2, 2.00018790482477e-13f);
    p = __fmaf_rn(p, x2, -8.60467152213735e-11f);
    p = __fmaf_rn(p, x2, 5.12229709037114e-08f);
    p = __fmaf_rn(p, x2, 1.48572235717979e-05f);
    p = __fmaf_rn(p, x2, 6.37261928875436e-04f);
    p = __fmaf_rn(p, x2, 4.89352455891786e-03f);
    float num = __fmul_rn(xc, p);
    float q = 1.19825839466702e-06f;
    q = __fmaf_rn(q, x2, 1.18534705686654e-04f);
    q = __fmaf_rn(q, x2, 2.26843463243900e-03f);
    q = __fmaf_rn(q, x2, 4.89352518554385e-03f);
    float r = __fdiv_rn(num, q);
    return (fabsf(x) < 0.0004f) ? x : r;
}

__device__ __forceinline__ float xla_sigmoid(float x) {
    return __fdiv_rn(1.0f, __fadd_rn(1.0f, xla_exp(-x)));
}

__device__ __forceinline__ float xla_softplus(float x) {
    return __fadd_rn(fmaxf(x, 0.0f), xla_log1p(xla_exp(-fabsf(x))));
}

// full per-bin log prob (used only by the cooperative extra-bin pass)
__device__ __forceinline__ float bin_logprob(int t, float m, float iv, float s) {
    if (t == 0) {
        float n0 = __fmul_rn(__fsub_rn(-0.9921875f, m), iv);
        return __fsub_rn(n0, xla_softplus(n0));
    }
    if (t == 255) {
        float n = __fmul_rn(__fsub_rn(0.9921875f, m), iv);
        return -xla_softplus(n);
    }
    float clo = __fadd_rn(__fmul_rn((float)t, 0.0078125f), -1.0f);
    float chi = __fadd_rn(__fmul_rn((float)(t + 1), 0.0078125f), -1.0f);
    float shi = xla_sigmoid(__fmul_rn(__fsub_rn(chi, m), iv));
    float slo = xla_sigmoid(__fmul_rn(__fsub_rn(clo, m), iv));
    float pdf = __fsub_rn(shi, slo);
    if (pdf > 1e-5f) {
        return xla_log(fmaxf(pdf, 1e-12f));
    }
    float midc = __fadd_rn(__fmul_rn((float)(2 * t + 1), 0.00390625f), -1.0f);
    float mid = __fmul_rn(__fsub_rn(midc, m), iv);
    float mlp = __fsub_rn(__fsub_rn(mid, s), __fmul_rn(2.0f, xla_softplus(mid)));
    return __fsub_rn(mlp, LOG127_5);
}

__global__ __launch_bounds__(32 * NWARPS)
void mixlogistic_decode_kernel(const float* __restrict__ x,
                               const float* __restrict__ l,
                               const int* __restrict__ epsp,
                               float* __restrict__ out,
                               int npix)
{
    __shared__ float sLOG[NWARPS][KMIX];
    __shared__ float sLPI[NWARPS][KMIX];
    __shared__ float sM  [NWARPS][3][KMIX];
    __shared__ float sS  [NWARPS][3][KMIX];
    __shared__ float sINV[NWARPS][3][KMIX];
    __shared__ float sCF [NWARPS][3][KMIX];
    __shared__ float sRED[NWARPS][2];

    const int warp = threadIdx.x >> 5;
    const int lane = threadIdx.x & 31;
    const int P = blockIdx.x * NWARPS + warp;
    if (P >= npix) return;

    const int b  = P >> 10;
    const int hw = P & (HW - 1);

    for (int c = lane; c < 100; c += 32) {
        float v = l[(size_t)(b * 100 + c) * HW + hw];
        if (c < KMIX) {
            sLOG[warp][c] = v;
        } else {
            int cc  = (c - KMIX) / 30;
            int rem = (c - KMIX) % 30;
            int grp = rem / KMIX;
            int k   = rem % KMIX;
            if (grp == 0) {
                sM[warp][cc][k] = v;
            } else if (grp == 1) {
                float s = fmaxf(v, -7.0f);
                sS[warp][cc][k]   = s;
                sINV[warp][cc][k] = xla_exp(-s);
            } else {
                sCF[warp][cc][k] = xla_tanh(v);
            }
        }
    }
    __syncwarp();
    if (lane == 0) {
        float mx = sLOG[warp][0];
        #pragma unroll
        for (int k = 1; k < KMIX; k++) mx = fmaxf(mx, sLOG[warp][k]);
        float sum = 0.0f;
        #pragma unroll
        for (int k = 0; k < KMIX; k++)
            sum = __fadd_rn(sum, xla_exp(__fsub_rn(sLOG[warp][k], mx)));
        sRED[warp][0] = mx;
        sRED[warp][1] = xla_log(sum);
    }
    __syncwarp();
    if (lane < KMIX) {
        sLPI[warp][lane] = __fsub_rn(__fsub_rn(sLOG[warp][lane], sRED[warp][0]),
                                     sRED[warp][1]);
    }
    __syncwarp();

    const int eps = epsp[0];
    float xr = 0.0f, xg = 0.0f;

    #pragma unroll
    for (int c = 0; c < 3; c++) {
        float xorig = x[(size_t)(b * 3 + c) * HW + hw];
        int r  = (int)(__fadd_rn(__fmul_rn(xorig, 127.5f), 127.5f));
        int lb = max(r - eps, 0);
        int ub = min(r + eps, 255);

        const int t0 = lb + lane;
        const bool v0 = (t0 <= ub);
        // upper boundary color for this lane's bin: colors[t0+1] (exact)
        const float chi = __fadd_rn(__fmul_rn((float)(t0 + 1), 0.0078125f), -1.0f);

        // ---- cooperative per-component precompute: lane k holds params of
        //      component k (m incl. coeff terms, iv, s, log_pi) ----
        float mk = 0.0f, ivk = 0.0f, sk = 0.0f, lpik = 0.0f;
        if (lane < KMIX) {
            mk = sM[warp][c][lane];
            if (c == 1) {
                mk = __fadd_rn(mk, __fmul_rn(sCF[warp][0][lane], xr));
            } else if (c == 2) {
                mk = __fadd_rn(mk, __fmul_rn(sCF[warp][1][lane], xr));
                mk = __fadd_rn(mk, __fmul_rn(sCF[warp][2][lane], xg));
            }
            ivk  = sINV[warp][c][lane];
            sk   = sS[warp][c][lane];
            lpik = sLPI[warp][lane];
        }

        // lower-boundary sigmoid for lane 0's bin: B_lb(k), needed iff lb >= 1
        float E = 0.0f;
        if (lb >= 1) {   // warp-uniform
            float cloLB = __fadd_rn(__fmul_rn((float)lb, 0.0078125f), -1.0f);
            E = xla_sigmoid(__fmul_rn(__fsub_rn(cloLB, mk), ivk));
        }

        // cooperative 33rd bin (te = lb+32): lane k computes component k
        const int te = lb + 32;
        const bool haveExtra = (te <= ub);    // warp-uniform
        float lpe = -INFINITY;
        if (haveExtra && lane < KMIX) {
            lpe = __fadd_rn(bin_logprob(te, mk, ivk, sk), lpik);
        }

        // ---- main 32 bins: one sigmoid per (lane, k); lower boundary shared
        //      from lane-1 via shuffle (bitwise-identical value) ----
        float lp0[KMIX];
        #pragma unroll
        for (int k = 0; k < KMIX; k++) {
            float m   = __shfl_sync(FULLMASK, mk,   k);
            float iv  = __shfl_sync(FULLMASK, ivk,  k);
            float s   = __shfl_sync(FULLMASK, sk,   k);
            float lpi = __shfl_sync(FULLMASK, lpik, k);
            float Ek  = __shfl_sync(FULLMASK, E,    k);

            float zhi = __fmul_rn(__fsub_rn(chi, m), iv);   // z(colors[t0+1])
            float S   = xla_sigmoid(zhi);                    // B_{t0+1}
            float slo = __shfl_up_sync(FULLMASK, S, 1);      // B_{t0} from lane-1
            if (lane == 0) slo = Ek;

            float lp;
            if (t0 == 0) {
                // n0 = z(colors[1]) == zhi for t0==0 (chi == -0.9921875 exactly)
                lp = __fsub_rn(zhi, xla_softplus(zhi));
            } else if (t0 == 255) {
                float zlo = __fmul_rn(__fsub_rn(0.9921875f, m), iv);
                lp = -xla_softplus(zlo);
            } else {
                float pdf = __fsub_rn(S, slo);
                if (pdf > 1e-5f) {
                    lp = xla_log(fmaxf(pdf, 1e-12f));
                } else {
                    float midc = __fadd_rn(__fmul_rn((float)(2 * t0 + 1), 0.00390625f), -1.0f);
                    float mid  = __fmul_rn(__fsub_rn(midc, m), iv);
                    float mlp  = __fsub_rn(__fsub_rn(mid, s),
                                           __fmul_rn(2.0f, xla_softplus(mid)));
                    lp = __fsub_rn(mlp, LOG127_5);
                }
            }
            lp0[k] = __fadd_rn(lp, lpi);
        }

        // per-bin logsumexp over k (sequential ascending k, like XLA reduce)
        float bv = -INFINITY;
        int   bt = 0x7FFFFFFF;
        if (v0) {
            float amax = lp0[0];
            #pragma unroll
            for (int k = 1; k < KMIX; k++) amax = fmaxf(amax, lp0[k]);
            float sum = 0.0f;
            #pragma unroll
            for (int k = 0; k < KMIX; k++)
                sum = __fadd_rn(sum, xla_exp(__fsub_rn(lp0[k], amax)));
            bv = __fadd_rn(xla_log(sum), amax);
            bt = t0;
        }

        // warp argmax (first-index tie semantics)
        #pragma unroll
        for (int off = 16; off; off >>= 1) {
            float ov = __shfl_down_sync(FULLMASK, bv, off);
            int   ot = __shfl_down_sync(FULLMASK, bt, off);
            if (ov > bv || (ov == bv && ot < bt)) { bv = ov; bt = ot; }
        }
        bv = __shfl_sync(FULLMASK, bv, 0);
        bt = __shfl_sync(FULLMASK, bt, 0);

        // extra-bin logsumexp: exact max (order-free), sequential ascending-k sum
        if (haveExtra) {
            float amax = lpe;
            #pragma unroll
            for (int off = 16; off; off >>= 1)
                amax = fmaxf(amax, __shfl_xor_sync(FULLMASK, amax, off));
            float e = xla_exp(__fsub_rn(lpe, amax));
            float sum = 0.0f;
            #pragma unroll
            for (int k = 0; k < KMIX; k++)
                sum = __fadd_rn(sum, __shfl_sync(FULLMASK, e, k));
            float val = __fadd_rn(xla_log(sum), amax);
            if (val > bv) { bv = val; bt = te; }   // te is largest index: strict >
        }

        float outv = __fdiv_rn(__fsub_rn((float)bt, 127.5f), 127.5f);
        if (c == 0) xr = outv;
        else if (c == 1) xg = outv;

        if (lane == 0) {
            out[(size_t)(b * 3 + c) * HW + hw] = outv;
        }
    }
}

extern "C" void kernel_launch(void* const* d_in, const int* in_sizes, int n_in,
                              void* d_out, int out_size)
{
    const float* x   = (const float*)d_in[0];
    const float* l   = (const float*)d_in[1];
    const int*   eps = (const int*)d_in[2];
    float* out = (float*)d_out;

    int npix = in_sizes[0] / 3;
    int blocks = (npix + NWARPS - 1) / NWARPS;
    mixlogistic_decode_kernel<<<blocks, 32 * NWARPS>>>(x, l, eps, out, npix);
}